// round 2
// baseline (speedup 1.0000x reference)
#include <cuda_runtime.h>
#include <math.h>

// ---------------------------------------------------------------------------
// Problem constants
// ---------------------------------------------------------------------------
namespace {
constexpr int NB = 64;          // batch
constexpr int NC = 3;           // channels
constexpr int HH = 224;         // H = W
constexpr int NPATCH = 49;      // 7x7 shuffle patches of 32
constexpr int KNOISE = 9408;    // 3*56*56

// scratch layout (floats)
constexpr size_t SZ_XS    = (size_t)NB * NC * HH * HH;       // 9,633,792
constexpr size_t OFF_XS   = 0;
constexpr size_t OFF_PBAR = OFF_XS + SZ_XS;                  // 2*64*588
constexpr size_t OFF_POSB = OFF_PBAR + 2 * 64 * 588;         // 1024
constexpr size_t OFF_NPOOL= OFF_POSB + 1024;                 // 64*9408
constexpr size_t OFF_M    = OFF_NPOOL + (size_t)64 * KNOISE; // 1024*1024
// zero-initialized contiguous region (atomic split-K accumulators):
constexpr size_t OFF_PRE  = OFF_M + (size_t)1024 * 1024;     // 128*1024
constexpr size_t OFF_FEATS= OFF_PRE + 128 * 1024;            // 192*1024
constexpr size_t OFF_DCT  = OFF_FEATS + 192 * 1024;
constexpr size_t OFF_Q    = OFF_DCT + 192 * 1024;
constexpr size_t OFF_K    = OFF_Q + 192 * 1024;
constexpr size_t OFF_V    = OFF_K + 192 * 1024;
constexpr size_t OFF_O    = OFF_V + 192 * 1024;
constexpr size_t ZERO_CNT = OFF_O + 192 * 1024 - OFF_PRE;    // 1,310,720
// plain-store buffers:
constexpr size_t OFF_TLN  = OFF_O + 192 * 1024;
constexpr size_t OFF_AV   = OFF_TLN + 192 * 1024;
constexpr size_t SCRATCH_TOTAL = OFF_AV + 192 * 1024;        // 13,064,704 floats
}

__device__ float g_scratch[SCRATCH_TOTAL];

// ---------------------------------------------------------------------------
// zero the split-K accumulator region
// ---------------------------------------------------------------------------
__global__ void zero_kernel(float* p, size_t n) {
    size_t i = (size_t)blockIdx.x * 256 + threadIdx.x;
    if (i < n) p[i] = 0.0f;
}

__device__ __forceinline__ float block_sum256(float v, float* sred) {
    int t = threadIdx.x;
    sred[t] = v;
    __syncthreads();
    for (int st = 128; st > 0; st >>= 1) {
        if (t < st) sred[t] += sred[t + st];
        __syncthreads();
    }
    float r = sred[0];
    __syncthreads();
    return r;
}

// ---------------------------------------------------------------------------
// 1. Patch shuffle: dest patch n <- src patch idx[n], then rot90^k, flips
// ---------------------------------------------------------------------------
__global__ __launch_bounds__(256) void shuffle_kernel(
    const float* __restrict__ x, const int* __restrict__ idx,
    const int* __restrict__ rot_k, const int* __restrict__ flip_h,
    const int* __restrict__ flip_w, float* __restrict__ xs)
{
    int blk = blockIdx.x;                 // b*49 + n
    int n = blk % NPATCH, b = blk / NPATCH;
    int s  = idx[n];
    int rk = rot_k[b * NPATCH + n];
    int fh = flip_h[b * NPATCH + n];
    int fw = flip_w[b * NPATCH + n];
    int nr = n / 7, nc = n % 7;
    int sr = s / 7, sc = s % 7;

    for (int t = threadIdx.x; t < NC * 32 * 32; t += 256) {
        int c = t >> 10;
        int rem = t & 1023;
        int u = rem >> 5, v = rem & 31;
        // flips applied last in reference -> invert first
        int up = fh ? 31 - u : u;
        int vp = fw ? 31 - v : v;
        int su, sv;
        switch (rk) {                     // numpy rot90 (CCW): out[i,j]=in[j,N-1-i]
            case 0: su = up;       sv = vp;       break;
            case 1: su = vp;       sv = 31 - up;  break;
            case 2: su = 31 - up;  sv = 31 - vp;  break;
            default:su = 31 - vp;  sv = up;       break;
        }
        xs[((size_t)(b * 3 + c) * 224 + nr * 32 + u) * 224 + nc * 32 + v] =
            x[((size_t)(b * 3 + c) * 224 + sr * 32 + su) * 224 + sc * 32 + sv];
    }
}

// ---------------------------------------------------------------------------
// 2. Token-mean folding: pbar[(br*64+b)*588 + c*196+i*14+j] =
//    mean over 16x16 token grid of img[b,c,ph*14+i,pw*14+j]
// ---------------------------------------------------------------------------
__global__ __launch_bounds__(196) void token_mean_kernel(
    const float* __restrict__ x, const float* __restrict__ xs,
    float* __restrict__ pbar)
{
    int blk = blockIdx.x;                 // br*192 + b*3 + c
    int c = blk % 3;
    int b = (blk / 3) % 64;
    int br = blk / 192;                   // 0 = shuffled, 1 = original
    const float* img = (br == 0) ? xs : x;
    int t = threadIdx.x;                  // 0..195
    int i = t / 14, j = t % 14;
    const float* base = img + (size_t)(b * 3 + c) * 224 * 224;
    float s = 0.0f;
    for (int ph = 0; ph < 16; ph++) {
        const float* rowp = base + (ph * 14 + i) * 224 + j;
        #pragma unroll
        for (int pw = 0; pw < 16; pw++) s += rowp[pw * 14];
    }
    pbar[(size_t)(br * 64 + b) * 588 + c * 196 + i * 14 + j] = s * (1.0f / 256.0f);
}

__global__ void posbar_kernel(const float* __restrict__ pos, float* __restrict__ posb) {
    int d = blockIdx.x * 256 + threadIdx.x;   // 1024 total
    float s = 0.0f;
    for (int t = 0; t < 256; t++) s += pos[t * 1024 + d];
    posb[d] = s * (1.0f / 256.0f);
}

// ---------------------------------------------------------------------------
// 3. Noise branch: npool = pool4(x) - pool8(x) (exact identity)
// ---------------------------------------------------------------------------
__global__ __launch_bounds__(256) void noise_pool_kernel(
    const float* __restrict__ x, float* __restrict__ npool)
{
    __shared__ float p4[3136];
    int bc = blockIdx.x;                  // b*3 + c
    int b = bc / 3, c = bc % 3;
    const float* base = x + (size_t)(b * 3 + c) * 224 * 224;
    int t = threadIdx.x;
    for (int i = t; i < 3136; i += 256) {
        int hp = i / 56, wp = i % 56;
        float s = 0.0f;
        #pragma unroll
        for (int r = 0; r < 4; r++)
            #pragma unroll
            for (int q = 0; q < 4; q++)
                s += base[(hp * 4 + r) * 224 + wp * 4 + q];
        p4[i] = s * (1.0f / 16.0f);
    }
    __syncthreads();
    for (int i = t; i < 3136; i += 256) {
        int hp = i / 56, wp = i % 56;
        int hb = (hp >> 1) << 1, wb = (wp >> 1) << 1;
        float p8 = 0.25f * (p4[hb * 56 + wb] + p4[hb * 56 + wb + 1] +
                            p4[(hb + 1) * 56 + wb] + p4[(hb + 1) * 56 + wb + 1]);
        npool[(size_t)b * KNOISE + c * 3136 + i] = p4[i] - p8;
    }
}

// ---------------------------------------------------------------------------
// 4. DCT-II (ortho) matrix; exact fp32 rounding order of reference
// ---------------------------------------------------------------------------
__global__ void dctmat_kernel(float* __restrict__ Mmat) {
    int id = blockIdx.x * 256 + threadIdx.x;   // 1M entries, M[k][j]
    int k = id >> 10, j = id & 1023;
    const float pif = 3.14159265358979323846f;
    float arg = ((pif * ((float)j + 0.5f)) * (float)k) * (1.0f / 1024.0f);
    float s = (k == 0) ? sqrtf(1.0f / 1024.0f) : sqrtf(2.0f / 1024.0f);
    Mmat[id] = cosf(arg) * s;
}

// ---------------------------------------------------------------------------
// 5. Tiled fp32 GEMM: C[m,n] (+)= sum_k A[m,k]*B[k,n]  (BT: B[n,k])
//    64x64 tile, BK=32, 4x4 register tile, split-K over blockIdx.z.
// ---------------------------------------------------------------------------
template <bool BT>
__global__ __launch_bounds__(256) void gemm64_kernel(
    const float* __restrict__ A, const float* __restrict__ B, float* __restrict__ C,
    int M, int N, int K, int lda, int ldb, int ldc, int kchunk)
{
    __shared__ float As[32][68];   // [kk][row]
    __shared__ float Bs[32][68];   // [kk][col]
    int row0 = blockIdx.y * 64;
    int col0 = blockIdx.x * 64;
    int kbeg = blockIdx.z * kchunk;
    int kend = min(K, kbeg + kchunk);
    int t  = threadIdx.x;
    int tx = t & 15, ty = t >> 4;
    float acc[4][4] = {};

    for (int kb = kbeg; kb < kend; kb += 32) {
        // A tile (64 rows x 32 k) -> transposed [kk][row]
        #pragma unroll
        for (int i = 0; i < 2; i++) {
            int q  = t + 256 * i;
            int k4 = q & 7, r = q >> 3;            // r < 64
            int kg = kb + k4 * 4;
            float4 av = make_float4(0.f, 0.f, 0.f, 0.f);
            if (kg + 3 < kend) {
                av = *reinterpret_cast<const float4*>(&A[(size_t)(row0 + r) * lda + kg]);
            } else if (kg < kend) {
                float tmp[4] = {0.f, 0.f, 0.f, 0.f};
                for (int e = 0; e < 4; e++)
                    if (kg + e < kend) tmp[e] = A[(size_t)(row0 + r) * lda + kg + e];
                av = make_float4(tmp[0], tmp[1], tmp[2], tmp[3]);
            }
            As[k4 * 4 + 0][r] = av.x; As[k4 * 4 + 1][r] = av.y;
            As[k4 * 4 + 2][r] = av.z; As[k4 * 4 + 3][r] = av.w;
        }
        // B tile
        if (!BT) {
            #pragma unroll
            for (int i = 0; i < 2; i++) {
                int q  = t + 256 * i;
                int c4 = q & 15, kk = q >> 4;      // kk < 32
                float4 bv = make_float4(0.f, 0.f, 0.f, 0.f);
                if (kb + kk < kend)
                    bv = *reinterpret_cast<const float4*>(&B[(size_t)(kb + kk) * ldb + col0 + c4 * 4]);
                Bs[kk][c4 * 4 + 0] = bv.x; Bs[kk][c4 * 4 + 1] = bv.y;
                Bs[kk][c4 * 4 + 2] = bv.z; Bs[kk][c4 * 4 + 3] = bv.w;
            }
        } else {
            #pragma unroll
            for (int i = 0; i < 2; i++) {
                int q  = t + 256 * i;
                int k4 = q & 7, c = q >> 3;        // c < 64
                int kg = kb + k4 * 4;
                float4 bv = make_float4(0.f, 0.f, 0.f, 0.f);
                if (kg + 3 < kend) {
                    bv = *reinterpret_cast<const float4*>(&B[(size_t)(col0 + c) * ldb + kg]);
                } else if (kg < kend) {
                    float tmp[4] = {0.f, 0.f, 0.f, 0.f};
                    for (int e = 0; e < 4; e++)
                        if (kg + e < kend) tmp[e] = B[(size_t)(col0 + c) * ldb + kg + e];
                    bv = make_float4(tmp[0], tmp[1], tmp[2], tmp[3]);
                }
                Bs[k4 * 4 + 0][c] = bv.x; Bs[k4 * 4 + 1][c] = bv.y;
                Bs[k4 * 4 + 2][c] = bv.z; Bs[k4 * 4 + 3][c] = bv.w;
            }
        }
        __syncthreads();
        #pragma unroll
        for (int kk = 0; kk < 32; kk++) {
            float a_[4], b_[4];
            #pragma unroll
            for (int e = 0; e < 4; e++) a_[e] = As[kk][ty * 4 + e];
            #pragma unroll
            for (int e = 0; e < 4; e++) b_[e] = Bs[kk][tx * 4 + e];
            #pragma unroll
            for (int i2 = 0; i2 < 4; i2++)
                #pragma unroll
                for (int j = 0; j < 4; j++)
                    acc[i2][j] += a_[i2] * b_[j];
        }
        __syncthreads();
    }
    bool single = (gridDim.z == 1);
    #pragma unroll
    for (int i2 = 0; i2 < 4; i2++) {
        int r = row0 + ty * 4 + i2;
        if (r < M) {
            size_t base = (size_t)r * ldc + col0 + tx * 4;
            #pragma unroll
            for (int j = 0; j < 4; j++) {
                if (single) C[base + j] = acc[i2][j];
                else        atomicAdd(&C[base + j], acc[i2][j]);
            }
        }
    }
}

// ---------------------------------------------------------------------------
// 6. LayerNorm kernels (rows of length 1024)
// ---------------------------------------------------------------------------
__global__ __launch_bounds__(256) void encode_ln_kernel(
    const float* __restrict__ pre, const float* __restrict__ posb,
    const float* __restrict__ g, const float* __restrict__ bb,
    float* __restrict__ feats)
{
    __shared__ float sred[256];
    int row = blockIdx.x;                 // 0..127 : br*64+b
    int br = row >> 6, b = row & 63;
    int t = threadIdx.x;
    float v[4]; float s = 0.0f;
    #pragma unroll
    for (int i = 0; i < 4; i++) {
        int d = t + 256 * i;
        v[i] = pre[(size_t)row * 1024 + d] + posb[d];
        s += v[i];
    }
    float mean = block_sum256(s, sred) * (1.0f / 1024.0f);
    float sq = 0.0f;
    #pragma unroll
    for (int i = 0; i < 4; i++) { float dd = v[i] - mean; sq += dd * dd; }
    float var = block_sum256(sq, sred) * (1.0f / 1024.0f);
    float rs = rsqrtf(var + 1e-5f);
    #pragma unroll
    for (int i = 0; i < 4; i++) {
        int d = t + 256 * i;
        feats[(size_t)b * 3072 + br * 1024 + d] = (v[i] - mean) * rs * g[d] + bb[d];
    }
}

__global__ __launch_bounds__(256) void ln_kernel(
    const float* __restrict__ in, const float* __restrict__ g,
    const float* __restrict__ bb, float* __restrict__ outp)
{
    __shared__ float sred[256];
    int row = blockIdx.x;
    int t = threadIdx.x;
    const float* p = in + (size_t)row * 1024;
    float v[4]; float s = 0.0f;
    #pragma unroll
    for (int i = 0; i < 4; i++) { v[i] = p[t + 256 * i]; s += v[i]; }
    float mean = block_sum256(s, sred) * (1.0f / 1024.0f);
    float sq = 0.0f;
    #pragma unroll
    for (int i = 0; i < 4; i++) { float dd = v[i] - mean; sq += dd * dd; }
    float var = block_sum256(sq, sred) * (1.0f / 1024.0f);
    float rs = rsqrtf(var + 1e-5f);
    #pragma unroll
    for (int i = 0; i < 4; i++) {
        int d = t + 256 * i;
        outp[(size_t)row * 1024 + d] = (v[i] - mean) * rs * g[d] + bb[d];
    }
}

// ---------------------------------------------------------------------------
// 7. 3-token attention per batch: scores -> softmax -> a@v
// ---------------------------------------------------------------------------
__global__ __launch_bounds__(256) void attn_kernel(
    const float* __restrict__ q, const float* __restrict__ k,
    const float* __restrict__ v, float* __restrict__ av)
{
    __shared__ float s_sc[9];
    __shared__ float s_a[9];
    int b = blockIdx.x, t = threadIdx.x;
    if (t < 9) s_sc[t] = 0.0f;
    __syncthreads();

    const float* qb = q + (size_t)b * 3072;
    const float* kb = k + (size_t)b * 3072;
    float acc[9] = {0, 0, 0, 0, 0, 0, 0, 0, 0};
    for (int d = t; d < 1024; d += 256) {
        float q0 = qb[d], q1 = qb[1024 + d], q2 = qb[2048 + d];
        float k0 = kb[d], k1 = kb[1024 + d], k2 = kb[2048 + d];
        acc[0] += q0 * k0; acc[1] += q0 * k1; acc[2] += q0 * k2;
        acc[3] += q1 * k0; acc[4] += q1 * k1; acc[5] += q1 * k2;
        acc[6] += q2 * k0; acc[7] += q2 * k1; acc[8] += q2 * k2;
    }
    #pragma unroll
    for (int i = 0; i < 9; i++) {
        float val = acc[i];
        #pragma unroll
        for (int o = 16; o > 0; o >>= 1) val += __shfl_xor_sync(0xffffffffu, val, o);
        if ((t & 31) == 0) atomicAdd(&s_sc[i], val);
    }
    __syncthreads();
    if (t < 3) {
        int n = t;
        float x0 = s_sc[n * 3 + 0] * 0.03125f;   // 1/sqrt(1024)
        float x1 = s_sc[n * 3 + 1] * 0.03125f;
        float x2 = s_sc[n * 3 + 2] * 0.03125f;
        float mx = fmaxf(x0, fmaxf(x1, x2));
        float e0 = expf(x0 - mx), e1 = expf(x1 - mx), e2 = expf(x2 - mx);
        float inv = 1.0f / (e0 + e1 + e2);
        s_a[n * 3 + 0] = e0 * inv; s_a[n * 3 + 1] = e1 * inv; s_a[n * 3 + 2] = e2 * inv;
    }
    __syncthreads();
    const float* vb = v + (size_t)b * 3072;
    float* ab = av + (size_t)b * 3072;
    for (int d = t; d < 1024; d += 256) {
        float v0 = vb[d], v1 = vb[1024 + d], v2 = vb[2048 + d];
        ab[d]        = s_a[0] * v0 + s_a[1] * v1 + s_a[2] * v2;
        ab[1024 + d] = s_a[3] * v0 + s_a[4] * v1 + s_a[5] * v2;
        ab[2048 + d] = s_a[6] * v0 + s_a[7] * v1 + s_a[8] * v2;
    }
}

// ---------------------------------------------------------------------------
// 8. Final: out[b] = mean_n(avWo[b,n,:] + dct[b,n,:]) . Wfc + bfc
// ---------------------------------------------------------------------------
__global__ __launch_bounds__(256) void final_kernel(
    const float* __restrict__ ob, const float* __restrict__ dct,
    const float* __restrict__ Wfc, const float* __restrict__ bfc,
    float* __restrict__ out)
{
    __shared__ float sred[256];
    int b = blockIdx.x, t = threadIdx.x;
    const float* o1 = ob + (size_t)b * 3072;
    const float* o2 = dct + (size_t)b * 3072;
    float acc = 0.0f;
    for (int d = t; d < 1024; d += 256) {
        float s = (o1[d] + o2[d]) + (o1[1024 + d] + o2[1024 + d])
                + (o1[2048 + d] + o2[2048 + d]);
        acc += s * Wfc[d];
    }
    float tot = block_sum256(acc, sred);
    if (t == 0) out[b] = tot * (1.0f / 3.0f) + bfc[0];
}

// ---------------------------------------------------------------------------
// Host launch
// ---------------------------------------------------------------------------
extern "C" void kernel_launch(void* const* d_in, const int* in_sizes, int n_in,
                              void* d_out, int out_size)
{
    const float* x    = (const float*)d_in[0];
    const int*   sidx = (const int*)  d_in[1];
    const int*   rot  = (const int*)  d_in[2];
    const int*   fh   = (const int*)  d_in[3];
    const int*   fw   = (const int*)  d_in[4];
    const float* Wpe  = (const float*)d_in[5];
    const float* pos  = (const float*)d_in[6];
    const float* lng  = (const float*)d_in[7];
    const float* lnb  = (const float*)d_in[8];
    const float* Wn   = (const float*)d_in[9];
    const float* Wq   = (const float*)d_in[10];
    const float* Wk   = (const float*)d_in[11];
    const float* Wv   = (const float*)d_in[12];
    const float* Wo   = (const float*)d_in[13];
    const float* ahg  = (const float*)d_in[14];
    const float* ahb  = (const float*)d_in[15];
    const float* Wfc  = (const float*)d_in[16];
    const float* bfc  = (const float*)d_in[17];
    float* out = (float*)d_out;

    void* sp = nullptr;
    cudaGetSymbolAddress(&sp, g_scratch);
    float* S     = (float*)sp;
    float* xs    = S + OFF_XS;
    float* pbar  = S + OFF_PBAR;
    float* posb  = S + OFF_POSB;
    float* npool = S + OFF_NPOOL;
    float* Mmat  = S + OFF_M;
    float* pre   = S + OFF_PRE;
    float* feats = S + OFF_FEATS;
    float* dct   = S + OFF_DCT;
    float* qb    = S + OFF_Q;
    float* kb    = S + OFF_K;
    float* vb    = S + OFF_V;
    float* ob    = S + OFF_O;
    float* tln   = S + OFF_TLN;
    float* av    = S + OFF_AV;

    // zero split-K accumulators (pre..ob contiguous)
    zero_kernel<<<(unsigned)((ZERO_CNT + 255) / 256), 256>>>(pre, ZERO_CNT);

    // independent prep
    shuffle_kernel<<<NB * NPATCH, 256>>>(x, sidx, rot, fh, fw, xs);
    token_mean_kernel<<<2 * NB * NC, 196>>>(x, xs, pbar);
    posbar_kernel<<<4, 256>>>(pos, posb);
    dctmat_kernel<<<4096, 256>>>(Mmat);
    noise_pool_kernel<<<NB * NC, 256>>>(x, npool);

    // patch-embed GEMM: (128 x 1024, K=588), split-K=3
    gemm64_kernel<false><<<dim3(16, 2, 3), 256>>>(
        pbar, Wpe, pre, 128, 1024, 588, 588, 1024, 1024, 196);
    encode_ln_kernel<<<128, 256>>>(pre, posb, lng, lnb, feats);

    // noise GEMM: (64 x 1024, K=9408), split-K=14, into feats branch 2
    gemm64_kernel<false><<<dim3(16, 1, 14), 256>>>(
        npool, Wn, feats + 2048, 64, 1024, KNOISE, KNOISE, 1024, 3072, 672);

    // DCT: (192 x 1024, K=1024), B transposed (Mmat rows = output index)
    gemm64_kernel<true><<<dim3(16, 3, 4), 256>>>(
        feats, Mmat, dct, 192, 1024, 1024, 1024, 1024, 1024, 256);

    // attention head
    ln_kernel<<<192, 256>>>(dct, ahg, ahb, tln);
    gemm64_kernel<false><<<dim3(16, 3, 4), 256>>>(
        tln, Wq, qb, 192, 1024, 1024, 1024, 1024, 1024, 256);
    gemm64_kernel<false><<<dim3(16, 3, 4), 256>>>(
        tln, Wk, kb, 192, 1024, 1024, 1024, 1024, 1024, 256);
    gemm64_kernel<false><<<dim3(16, 3, 4), 256>>>(
        tln, Wv, vb, 192, 1024, 1024, 1024, 1024, 1024, 256);
    attn_kernel<<<NB, 256>>>(qb, kb, vb, av);
    gemm64_kernel<false><<<dim3(16, 3, 4), 256>>>(
        av, Wo, ob, 192, 1024, 1024, 1024, 1024, 1024, 256);

    final_kernel<<<NB, 256>>>(ob, dct, Wfc, bfc, out);
}

// round 8
// speedup vs baseline: 1.3738x; 1.3738x over previous
#include <cuda_runtime.h>
#include <math.h>

// ---------------------------------------------------------------------------
// Problem constants
// ---------------------------------------------------------------------------
namespace {
constexpr int NB = 64;          // batch
constexpr int NC = 3;           // channels
constexpr int HH = 224;         // H = W
constexpr int NPATCH = 49;      // 7x7 shuffle patches of 32
constexpr int KNOISE = 9408;    // 3*56*56

// scratch layout (floats)
constexpr size_t SZ_XS    = (size_t)NB * NC * HH * HH;       // 9,633,792
constexpr size_t OFF_XS   = 0;
constexpr size_t OFF_PBAR = OFF_XS + SZ_XS;                  // 2*64*588
constexpr size_t OFF_POSB = OFF_PBAR + 2 * 64 * 588;         // 1024
constexpr size_t OFF_NPOOL= OFF_POSB + 1024;                 // 64*9408
constexpr size_t OFF_M    = OFF_NPOOL + (size_t)64 * KNOISE; // 1024*1024
// zero-initialized contiguous region (atomic split-K accumulators):
constexpr size_t OFF_PRE  = OFF_M + (size_t)1024 * 1024;     // 128*1024
constexpr size_t OFF_FEATS= OFF_PRE + 128 * 1024;            // 192*1024
constexpr size_t OFF_DCT  = OFF_FEATS + 192 * 1024;
constexpr size_t OFF_Q    = OFF_DCT + 192 * 1024;
constexpr size_t OFF_K    = OFF_Q + 192 * 1024;
constexpr size_t ZERO_CNT = OFF_K + 192 * 1024 - OFF_PRE;    // 917,504
// plain-store buffers:
constexpr size_t OFF_TLN  = OFF_K + 192 * 1024;
constexpr size_t OFF_W1   = OFF_TLN + 192 * 1024;
constexpr size_t OFF_W2   = OFF_W1 + 1024;
constexpr size_t SCRATCH_TOTAL = OFF_W2 + 1024;
}

__device__ float g_scratch[SCRATCH_TOTAL];

// ---------------------------------------------------------------------------
// zero the split-K accumulator region
// ---------------------------------------------------------------------------
__global__ void zero_kernel(float* p, size_t n) {
    size_t i = (size_t)blockIdx.x * 256 + threadIdx.x;
    if (i < n) p[i] = 0.0f;
}

// ---------------------------------------------------------------------------
// matvec: out[r] = sum_j Mat[r,j] * vec[j]   (1024x1024 * 1024)
// ---------------------------------------------------------------------------
__global__ __launch_bounds__(256) void matvec_kernel(
    const float* __restrict__ Mat, const float* __restrict__ vec,
    float* __restrict__ outv)
{
    int w = threadIdx.x >> 5, lane = threadIdx.x & 31;
    int row = blockIdx.x * 8 + w;
    const float* mp = Mat + (size_t)row * 1024;
    float s = 0.0f;
    #pragma unroll
    for (int j = lane; j < 1024; j += 32) s += mp[j] * vec[j];
    #pragma unroll
    for (int o = 16; o > 0; o >>= 1) s += __shfl_xor_sync(0xffffffffu, s, o);
    if (lane == 0) outv[row] = s;
}

// ---------------------------------------------------------------------------
// 1. Patch shuffle: dest patch n <- src patch idx[n], then rot90^k, flips
// ---------------------------------------------------------------------------
__global__ __launch_bounds__(256) void shuffle_kernel(
    const float* __restrict__ x, const int* __restrict__ idx,
    const int* __restrict__ rot_k, const int* __restrict__ flip_h,
    const int* __restrict__ flip_w, float* __restrict__ xs)
{
    int blk = blockIdx.x;                 // b*49 + n
    int n = blk % NPATCH, b = blk / NPATCH;
    int s  = idx[n];
    int rk = rot_k[b * NPATCH + n];
    int fh = flip_h[b * NPATCH + n];
    int fw = flip_w[b * NPATCH + n];
    int nr = n / 7, nc = n % 7;
    int sr = s / 7, sc = s % 7;

    for (int t = threadIdx.x; t < NC * 32 * 32; t += 256) {
        int c = t >> 10;
        int rem = t & 1023;
        int u = rem >> 5, v = rem & 31;
        int up = fh ? 31 - u : u;
        int vp = fw ? 31 - v : v;
        int su, sv;
        switch (rk) {                     // numpy rot90 (CCW)
            case 0: su = up;       sv = vp;       break;
            case 1: su = vp;       sv = 31 - up;  break;
            case 2: su = 31 - up;  sv = 31 - vp;  break;
            default:su = 31 - vp;  sv = up;       break;
        }
        xs[((size_t)(b * 3 + c) * 224 + nr * 32 + u) * 224 + nc * 32 + v] =
            x[((size_t)(b * 3 + c) * 224 + sr * 32 + su) * 224 + sc * 32 + sv];
    }
}

// ---------------------------------------------------------------------------
// 2. Token-mean folding, coalesced: pbar[(br*64+b)*588 + c*196+i*14+j]
//    = mean over 16x16 token grid of img[b,c,ph*14+i,pw*14+j]
// ---------------------------------------------------------------------------
__global__ __launch_bounds__(224) void token_mean_kernel(
    const float* __restrict__ x, const float* __restrict__ xs,
    float* __restrict__ pbar)
{
    __shared__ float s[224];
    int blk = blockIdx.x;                 // br*192 + b*3 + c
    int c = blk % 3;
    int b = (blk / 3) % 64;
    int br = blk / 192;                   // 0 = shuffled, 1 = original
    const float* img = (br == 0) ? xs : x;
    const float* base = img + (size_t)(b * 3 + c) * 224 * 224;
    int t = threadIdx.x;                  // column 0..223
    size_t orow = (size_t)(br * 64 + b) * 588 + c * 196;

    for (int i = 0; i < 14; i++) {
        float acc = 0.0f;
        #pragma unroll
        for (int ph = 0; ph < 16; ph++)
            acc += base[(ph * 14 + i) * 224 + t];
        s[t] = acc;
        __syncthreads();
        if (t < 14) {                     // j = t
            float tot = 0.0f;
            #pragma unroll
            for (int pw = 0; pw < 16; pw++) tot += s[t + 14 * pw];
            pbar[orow + i * 14 + t] = tot * (1.0f / 256.0f);
        }
        __syncthreads();
    }
}

// ---------------------------------------------------------------------------
// 2b. pos-emb token mean, parallel: 32 blocks x 256 threads
// ---------------------------------------------------------------------------
__global__ __launch_bounds__(256) void posbar_kernel(
    const float* __restrict__ pos, float* __restrict__ posb)
{
    __shared__ float sm[8][32];
    int d0 = blockIdx.x * 32;
    int c  = threadIdx.x & 31;            // column within chunk
    int rg = threadIdx.x >> 5;            // 8 row groups of 32
    float s = 0.0f;
    #pragma unroll
    for (int r = rg * 32; r < rg * 32 + 32; r++)
        s += pos[(size_t)r * 1024 + d0 + c];
    sm[rg][c] = s;
    __syncthreads();
    if (rg == 0) {
        float tot = 0.0f;
        #pragma unroll
        for (int i = 0; i < 8; i++) tot += sm[i][c];
        posb[d0 + c] = tot * (1.0f / 256.0f);
    }
}

// ---------------------------------------------------------------------------
// 3. Noise branch: npool = pool4(x) - pool8(x) (exact identity)
// ---------------------------------------------------------------------------
__global__ __launch_bounds__(256) void noise_pool_kernel(
    const float* __restrict__ x, float* __restrict__ npool)
{
    __shared__ float p4[3136];
    int bc = blockIdx.x;                  // b*3 + c
    int b = bc / 3, c = bc % 3;
    const float* base = x + (size_t)(b * 3 + c) * 224 * 224;
    int t = threadIdx.x;
    for (int i = t; i < 3136; i += 256) {
        int hp = i / 56, wp = i % 56;
        float s = 0.0f;
        #pragma unroll
        for (int r = 0; r < 4; r++) {
            float4 v4 = *reinterpret_cast<const float4*>(
                &base[(hp * 4 + r) * 224 + wp * 4]);
            s += (v4.x + v4.y) + (v4.z + v4.w);
        }
        p4[i] = s * (1.0f / 16.0f);
    }
    __syncthreads();
    for (int i = t; i < 3136; i += 256) {
        int hp = i / 56, wp = i % 56;
        int hb = (hp >> 1) << 1, wb = (wp >> 1) << 1;
        float p8 = 0.25f * (p4[hb * 56 + wb] + p4[hb * 56 + wb + 1] +
                            p4[(hb + 1) * 56 + wb] + p4[(hb + 1) * 56 + wb + 1]);
        npool[(size_t)b * KNOISE + c * 3136 + i] = p4[i] - p8;
    }
}

// ---------------------------------------------------------------------------
// 4. DCT-II (ortho) matrix; exact fp32 rounding order of reference
// ---------------------------------------------------------------------------
__global__ void dctmat_kernel(float* __restrict__ Mmat) {
    int id = blockIdx.x * 256 + threadIdx.x;   // 1M entries, M[k][j]
    int k = id >> 10, j = id & 1023;
    const float pif = 3.14159265358979323846f;
    float arg = ((pif * ((float)j + 0.5f)) * (float)k) * (1.0f / 1024.0f);
    float s = (k == 0) ? sqrtf(1.0f / 1024.0f) : sqrtf(2.0f / 1024.0f);
    Mmat[id] = cosf(arg) * s;
}

// ---------------------------------------------------------------------------
// 5. Tiled fp32 GEMM: C[m,n] (+)= sum_k A[m,k]*B[k,n]  (BT: B[n,k])
//    64x64 tile, BK=32, 4x4 register tile, split-K over blockIdx.z.
//    DUAL: two (B,C) pairs selected by blockIdx.z / zsplit (for fused q,k).
// ---------------------------------------------------------------------------
template <bool BT, bool DUAL>
__global__ __launch_bounds__(256) void gemm64_kernel(
    const float* __restrict__ A,
    const float* __restrict__ B0, const float* __restrict__ B1,
    float* __restrict__ C0, float* __restrict__ C1,
    int M, int N, int K, int lda, int ldb, int ldc, int kchunk, int zsplit)
{
    __shared__ float As[32][68];   // [kk][row]
    __shared__ float Bs[32][68];   // [kk][col]
    const float* B = B0;
    float* C = C0;
    int zz = blockIdx.z;
    if (DUAL) {
        if (zz >= zsplit) { B = B1; C = C1; zz -= zsplit; }
    }
    int row0 = blockIdx.y * 64;
    int col0 = blockIdx.x * 64;
    int kbeg = zz * kchunk;
    int kend = min(K, kbeg + kchunk);
    int t  = threadIdx.x;
    int tx = t & 15, ty = t >> 4;
    float acc[4][4] = {};

    for (int kb = kbeg; kb < kend; kb += 32) {
        // A tile (64 rows x 32 k) -> transposed [kk][row]
        #pragma unroll
        for (int i = 0; i < 2; i++) {
            int q  = t + 256 * i;
            int k4 = q & 7, r = q >> 3;            // r < 64
            int kg = kb + k4 * 4;
            float4 av = make_float4(0.f, 0.f, 0.f, 0.f);
            if (kg + 3 < kend) {
                av = *reinterpret_cast<const float4*>(&A[(size_t)(row0 + r) * lda + kg]);
            } else if (kg < kend) {
                float tmp[4] = {0.f, 0.f, 0.f, 0.f};
                for (int e = 0; e < 4; e++)
                    if (kg + e < kend) tmp[e] = A[(size_t)(row0 + r) * lda + kg + e];
                av = make_float4(tmp[0], tmp[1], tmp[2], tmp[3]);
            }
            As[k4 * 4 + 0][r] = av.x; As[k4 * 4 + 1][r] = av.y;
            As[k4 * 4 + 2][r] = av.z; As[k4 * 4 + 3][r] = av.w;
        }
        // B tile
        if (!BT) {
            #pragma unroll
            for (int i = 0; i < 2; i++) {
                int q  = t + 256 * i;
                int c4 = q & 15, kk = q >> 4;      // kk < 32
                float4 bv = make_float4(0.f, 0.f, 0.f, 0.f);
                if (kb + kk < kend)
                    bv = *reinterpret_cast<const float4*>(&B[(size_t)(kb + kk) * ldb + col0 + c4 * 4]);
                Bs[kk][c4 * 4 + 0] = bv.x; Bs[kk][c4 * 4 + 1] = bv.y;
                Bs[kk][c4 * 4 + 2] = bv.z; Bs[kk][c4 * 4 + 3] = bv.w;
            }
        } else {
            #pragma unroll
            for (int i = 0; i < 2; i++) {
                int q  = t + 256 * i;
                int k4 = q & 7, c = q >> 3;        // c < 64
                int kg = kb + k4 * 4;
                float4 bv = make_float4(0.f, 0.f, 0.f, 0.f);
                if (kg + 3 < kend) {
                    bv = *reinterpret_cast<const float4*>(&B[(size_t)(col0 + c) * ldb + kg]);
                } else if (kg < kend) {
                    float tmp[4] = {0.f, 0.f, 0.f, 0.f};
                    for (int e = 0; e < 4; e++)
                        if (kg + e < kend) tmp[e] = B[(size_t)(col0 + c) * ldb + kg + e];
                    bv = make_float4(tmp[0], tmp[1], tmp[2], tmp[3]);
                }
                Bs[k4 * 4 + 0][c] = bv.x; Bs[k4 * 4 + 1][c] = bv.y;
                Bs[k4 * 4 + 2][c] = bv.z; Bs[k4 * 4 + 3][c] = bv.w;
            }
        }
        __syncthreads();
        #pragma unroll
        for (int kk = 0; kk < 32; kk++) {
            float4 a4 = *reinterpret_cast<const float4*>(&As[kk][ty * 4]);
            float4 b4 = *reinterpret_cast<const float4*>(&Bs[kk][tx * 4]);
            float a_[4] = {a4.x, a4.y, a4.z, a4.w};
            float b_[4] = {b4.x, b4.y, b4.z, b4.w};
            #pragma unroll
            for (int i2 = 0; i2 < 4; i2++)
                #pragma unroll
                for (int j = 0; j < 4; j++)
                    acc[i2][j] += a_[i2] * b_[j];
        }
        __syncthreads();
    }
    bool single = (!DUAL) && (gridDim.z == 1);
    #pragma unroll
    for (int i2 = 0; i2 < 4; i2++) {
        int r = row0 + ty * 4 + i2;
        if (r < M) {
            size_t base = (size_t)r * ldc + col0 + tx * 4;
            #pragma unroll
            for (int j = 0; j < 4; j++) {
                if (single) C[base + j] = acc[i2][j];
                else        atomicAdd(&C[base + j], acc[i2][j]);
            }
        }
    }
}

// ---------------------------------------------------------------------------
// 6. LayerNorm kernels (rows of length 1024)
// ---------------------------------------------------------------------------
__device__ __forceinline__ float block_sum256(float v, float* sred) {
    int t = threadIdx.x;
    sred[t] = v;
    __syncthreads();
    for (int st = 128; st > 0; st >>= 1) {
        if (t < st) sred[t] += sred[t + st];
        __syncthreads();
    }
    float r = sred[0];
    __syncthreads();
    return r;
}

__global__ __launch_bounds__(256) void encode_ln_kernel(
    const float* __restrict__ pre, const float* __restrict__ posb,
    const float* __restrict__ g, const float* __restrict__ bb,
    float* __restrict__ feats)
{
    __shared__ float sred[256];
    int row = blockIdx.x;                 // 0..127 : br*64+b
    int br = row >> 6, b = row & 63;
    int t = threadIdx.x;
    float v[4]; float s = 0.0f;
    #pragma unroll
    for (int i = 0; i < 4; i++) {
        int d = t + 256 * i;
        v[i] = pre[(size_t)row * 1024 + d] + posb[d];
        s += v[i];
    }
    float mean = block_sum256(s, sred) * (1.0f / 1024.0f);
    float sq = 0.0f;
    #pragma unroll
    for (int i = 0; i < 4; i++) { float dd = v[i] - mean; sq += dd * dd; }
    float var = block_sum256(sq, sred) * (1.0f / 1024.0f);
    float rs = rsqrtf(var + 1e-5f);
    #pragma unroll
    for (int i = 0; i < 4; i++) {
        int d = t + 256 * i;
        feats[(size_t)b * 3072 + br * 1024 + d] = (v[i] - mean) * rs * g[d] + bb[d];
    }
}

__global__ __launch_bounds__(256) void ln_kernel(
    const float* __restrict__ in, const float* __restrict__ g,
    const float* __restrict__ bb, float* __restrict__ outp)
{
    __shared__ float sred[256];
    int row = blockIdx.x;
    int t = threadIdx.x;
    const float* p = in + (size_t)row * 1024;
    float v[4]; float s = 0.0f;
    #pragma unroll
    for (int i = 0; i < 4; i++) { v[i] = p[t + 256 * i]; s += v[i]; }
    float mean = block_sum256(s, sred) * (1.0f / 1024.0f);
    float sq = 0.0f;
    #pragma unroll
    for (int i = 0; i < 4; i++) { float dd = v[i] - mean; sq += dd * dd; }
    float var = block_sum256(sq, sred) * (1.0f / 1024.0f);
    float rs = rsqrtf(var + 1e-5f);
    #pragma unroll
    for (int i = 0; i < 4; i++) {
        int d = t + 256 * i;
        outp[(size_t)row * 1024 + d] = (v[i] - mean) * rs * g[d] + bb[d];
    }
}

// ---------------------------------------------------------------------------
// 7. Fused attention + epilogue, one block per batch:
//    scores = q k^T / 32; a = softmax(scores)
//    out[b] = (1/3) * Sum_n [ Sum_m a[n,m]*(tln[b,m].w2) + dct[b,n].Wfc ] + bfc
// ---------------------------------------------------------------------------
__global__ __launch_bounds__(256) void attn_final_kernel(
    const float* __restrict__ q, const float* __restrict__ k,
    const float* __restrict__ tln, const float* __restrict__ dct,
    const float* __restrict__ w2, const float* __restrict__ Wfc,
    const float* __restrict__ bfc, float* __restrict__ out)
{
    __shared__ float red[15];             // 9 scores, 3 vproj, 3 dct dots
    int b = blockIdx.x, t = threadIdx.x;
    if (t < 15) red[t] = 0.0f;
    __syncthreads();

    const float* qb = q   + (size_t)b * 3072;
    const float* kb = k   + (size_t)b * 3072;
    const float* tb = tln + (size_t)b * 3072;
    const float* db = dct + (size_t)b * 3072;
    float acc[15];
    #pragma unroll
    for (int i = 0; i < 15; i++) acc[i] = 0.0f;

    for (int d = t; d < 1024; d += 256) {
        float q0 = qb[d], q1 = qb[1024 + d], q2 = qb[2048 + d];
        float k0 = kb[d], k1 = kb[1024 + d], k2 = kb[2048 + d];
        acc[0] += q0 * k0; acc[1] += q0 * k1; acc[2] += q0 * k2;
        acc[3] += q1 * k0; acc[4] += q1 * k1; acc[5] += q1 * k2;
        acc[6] += q2 * k0; acc[7] += q2 * k1; acc[8] += q2 * k2;
        float w2d = w2[d], wfd = Wfc[d];
        acc[9]  += tb[d] * w2d; acc[10] += tb[1024 + d] * w2d; acc[11] += tb[2048 + d] * w2d;
        acc[12] += db[d] * wfd; acc[13] += db[1024 + d] * wfd; acc[14] += db[2048 + d] * wfd;
    }
    #pragma unroll
    for (int i = 0; i < 15; i++) {
        float val = acc[i];
        #pragma unroll
        for (int o = 16; o > 0; o >>= 1) val += __shfl_xor_sync(0xffffffffu, val, o);
        if ((t & 31) == 0) atomicAdd(&red[i], val);
    }
    __syncthreads();
    if (t == 0) {
        float tok = 0.0f;
        #pragma unroll
        for (int n = 0; n < 3; n++) {
            float x0 = red[n * 3 + 0] * 0.03125f;   // 1/sqrt(1024)
            float x1 = red[n * 3 + 1] * 0.03125f;
            float x2 = red[n * 3 + 2] * 0.03125f;
            float mx = fmaxf(x0, fmaxf(x1, x2));
            float e0 = expf(x0 - mx), e1 = expf(x1 - mx), e2 = expf(x2 - mx);
            float inv = 1.0f / (e0 + e1 + e2);
            tok += (e0 * red[9] + e1 * red[10] + e2 * red[11]) * inv;
        }
        float dsum = red[12] + red[13] + red[14];
        out[b] = (tok + dsum) * (1.0f / 3.0f) + bfc[0];
    }
}

// ---------------------------------------------------------------------------
// Host launch
// ---------------------------------------------------------------------------
extern "C" void kernel_launch(void* const* d_in, const int* in_sizes, int n_in,
                              void* d_out, int out_size)
{
    const float* x    = (const float*)d_in[0];
    const int*   sidx = (const int*)  d_in[1];
    const int*   rot  = (const int*)  d_in[2];
    const int*   fh   = (const int*)  d_in[3];
    const int*   fw   = (const int*)  d_in[4];
    const float* Wpe  = (const float*)d_in[5];
    const float* pos  = (const float*)d_in[6];
    const float* lng  = (const float*)d_in[7];
    const float* lnb  = (const float*)d_in[8];
    const float* Wn   = (const float*)d_in[9];
    const float* Wq   = (const float*)d_in[10];
    const float* Wk   = (const float*)d_in[11];
    const float* Wv   = (const float*)d_in[12];
    const float* Wo   = (const float*)d_in[13];
    const float* ahg  = (const float*)d_in[14];
    const float* ahb  = (const float*)d_in[15];
    const float* Wfc  = (const float*)d_in[16];
    const float* bfc  = (const float*)d_in[17];
    float* out = (float*)d_out;

    void* sp = nullptr;
    cudaGetSymbolAddress(&sp, g_scratch);
    float* S     = (float*)sp;
    float* xs    = S + OFF_XS;
    float* pbar  = S + OFF_PBAR;
    float* posb  = S + OFF_POSB;
    float* npool = S + OFF_NPOOL;
    float* Mmat  = S + OFF_M;
    float* pre   = S + OFF_PRE;
    float* feats = S + OFF_FEATS;
    float* dct   = S + OFF_DCT;
    float* qb    = S + OFF_Q;
    float* kb    = S + OFF_K;
    float* tln   = S + OFF_TLN;
    float* w1    = S + OFF_W1;
    float* w2    = S + OFF_W2;

    // zero split-K accumulators (pre, feats, dct, q, k contiguous)
    zero_kernel<<<(unsigned)((ZERO_CNT + 255) / 256), 256>>>(pre, ZERO_CNT);

    // folded weight vectors: w1 = Wo @ Wfc ; w2 = Wv @ w1
    matvec_kernel<<<128, 256>>>(Wo, Wfc, w1);
    matvec_kernel<<<128, 256>>>(Wv, w1, w2);

    // independent prep
    shuffle_kernel<<<NB * NPATCH, 256>>>(x, sidx, rot, fh, fw, xs);
    token_mean_kernel<<<2 * NB * NC, 224>>>(x, xs, pbar);
    posbar_kernel<<<32, 256>>>(pos, posb);
    dctmat_kernel<<<4096, 256>>>(Mmat);
    noise_pool_kernel<<<NB * NC, 256>>>(x, npool);

    // patch-embed GEMM: (128 x 1024, K=588), split-K=3
    gemm64_kernel<false, false><<<dim3(16, 2, 3), 256>>>(
        pbar, Wpe, nullptr, pre, nullptr, 128, 1024, 588, 588, 1024, 1024, 196, 3);
    encode_ln_kernel<<<128, 256>>>(pre, posb, lng, lnb, feats);

    // noise GEMM: (64 x 1024, K=9408), split-K=21, into feats branch 2
    gemm64_kernel<false, false><<<dim3(16, 1, 21), 256>>>(
        npool, Wn, nullptr, feats + 2048, nullptr,
        64, 1024, KNOISE, KNOISE, 1024, 3072, 448, 21);

    // DCT: (192 x 1024, K=1024), B transposed, split-K=8
    gemm64_kernel<true, false><<<dim3(16, 3, 8), 256>>>(
        feats, Mmat, nullptr, dct, nullptr,
        192, 1024, 1024, 1024, 1024, 1024, 128, 8);

    // attention head
    ln_kernel<<<192, 256>>>(dct, ahg, ahb, tln);
    // fused q & k GEMMs: grid.z = 16 (8 split-K chunks per weight)
    gemm64_kernel<false, true><<<dim3(16, 3, 16), 256>>>(
        tln, Wq, Wk, qb, kb, 192, 1024, 1024, 1024, 1024, 1024, 128, 8);

    attn_final_kernel<<<NB, 256>>>(qb, kb, tln, dct, w2, Wfc, bfc, out);
}